// round 16
// baseline (speedup 1.0000x reference)
#include <cuda_runtime.h>
#include <cuda_bf16.h>
#include <math.h>
#include <stdint.h>

// ---------------- problem constants ----------------
#define BB    8
#define MM    1024
#define DM    768
#define HH    12
#define DHD   64
#define RR    32
#define RFF   384
#define DFF   3072
#define BMTOT (BB*MM)          // 8192
#define NCAT  (3*HH*RR)        // 1152

typedef __nv_bfloat16 bf16;
typedef __nv_bfloat162 bf162;

// ---------------- scratch (device globals; no allocs allowed) ----------------
__device__ float g_T   [BMTOT* NCAT];     // x@Pt; later reused as split-K partial buffer
__device__ float g_Q   [BMTOT* DM];       // reused as split bf16 Qhi|Qlo
__device__ float g_K   [BMTOT* DM];       // reused as split bf16 Khi|Klo
__device__ float g_V   [BMTOT* DM];       // reused as split bf16 Vhi|Vlo
__device__ float g_tmp [BMTOT* DM];
__device__ float g_x1  [BMTOT* DM];
__device__ bf16 g_xs_hi [BMTOT*DM],  g_xs_lo [BMTOT*DM];
__device__ bf16 g_as_hi [BMTOT*DM],  g_as_lo [BMTOT*DM];
__device__ bf16 g_ms_hi [BMTOT*RFF], g_ms_lo [BMTOT*RFF];
__device__ bf16 g_x1s_hi[BMTOT*DM],  g_x1s_lo[BMTOT*DM];
__device__ bf16 g_hs_hi [BMTOT*DFF], g_hs_lo [BMTOT*DFF];
__device__ bf16 g_ptT_hi[NCAT*DM],  g_ptT_lo[NCAT*DM];
__device__ bf16 g_uoT_hi[RFF*DM],   g_uoT_lo[RFF*DM];
__device__ bf16 g_voT_hi[DM*RFF],   g_voT_lo[DM*RFF];
__device__ bf16 g_u1T_hi[RFF*DM],   g_u1T_lo[RFF*DM];
__device__ bf16 g_v1T_hi[DFF*RFF],  g_v1T_lo[DFF*RFF];
__device__ bf16 g_u2T_hi[RFF*DFF],  g_u2T_lo[RFF*DFF];
__device__ bf16 g_v2T_hi[DM*RFF],   g_v2T_lo[DM*RFF];

// ---------------- helpers ----------------
__device__ __forceinline__ float gelu_exact(float v) {
    return 0.5f * v * (1.0f + erff(v * 0.70710678118654752440f));
}

__device__ __forceinline__ void split2(float v, bf16& h, bf16& l) {
    h = __float2bfloat16(v);
    l = __float2bfloat16(v - __bfloat162float(h));
}

__device__ __forceinline__ void split_pack(float a, float b, uint32_t& hi, uint32_t& lo) {
    bf16 ha, la, hb, lb;
    split2(a, ha, la); split2(b, hb, lb);
    bf162 th(ha, hb), tl(la, lb);
    hi = *(uint32_t*)&th; lo = *(uint32_t*)&tl;
}

__device__ __forceinline__ uint32_t smem_u32(const void* p) {
    uint32_t a;
    asm("{ .reg .u64 t; cvta.to.shared.u64 t, %1; cvt.u32.u64 %0, t; }" : "=r"(a) : "l"(p));
    return a;
}

__device__ __forceinline__ void ldsm4(uint32_t* r, uint32_t addr) {
    asm volatile("ldmatrix.sync.aligned.m8n8.x4.shared.b16 {%0,%1,%2,%3}, [%4];"
                 : "=r"(r[0]), "=r"(r[1]), "=r"(r[2]), "=r"(r[3]) : "r"(addr));
}
__device__ __forceinline__ void ldsm4t(uint32_t* r, uint32_t addr) {
    asm volatile("ldmatrix.sync.aligned.m8n8.x4.trans.shared.b16 {%0,%1,%2,%3}, [%4];"
                 : "=r"(r[0]), "=r"(r[1]), "=r"(r[2]), "=r"(r[3]) : "r"(addr));
}

__device__ __forceinline__ void mma16816(float* d, const uint32_t* a, const uint32_t* b) {
    asm volatile(
        "mma.sync.aligned.m16n8k16.row.col.f32.bf16.bf16.f32 "
        "{%0,%1,%2,%3}, {%4,%5,%6,%7}, {%8,%9}, {%0,%1,%2,%3};"
        : "+f"(d[0]), "+f"(d[1]), "+f"(d[2]), "+f"(d[3])
        : "r"(a[0]), "r"(a[1]), "r"(a[2]), "r"(a[3]), "r"(b[0]), "r"(b[1]));
}

__device__ __forceinline__ void cp16(uint32_t dst, const void* src) {
    asm volatile("cp.async.cg.shared.global [%0], [%1], 16;" :: "r"(dst), "l"(src));
}
__device__ __forceinline__ void cp_commit() {
    asm volatile("cp.async.commit_group;" ::: "memory");
}
template<int N>
__device__ __forceinline__ void cp_wait() {
    asm volatile("cp.async.wait_group %0;" :: "n"(N) : "memory");
}

// ---------------- fused weight/activation conversion ----------------
struct ConvSeg { const float* src; bf16* hi; bf16* lo; int K; int N; int start; };
struct ConvArgs { ConvSeg seg[7]; int total; };

__global__ void fused_convert_kernel(ConvArgs a) {
    const int w = blockIdx.x * 256 + threadIdx.x;
    if (w >= a.total) return;
    int s = 0;
    #pragma unroll
    for (int i = 1; i < 7; i++)
        if (w >= a.seg[i].start) s = i;
    const ConvSeg sg = a.seg[s];
    const int local = w - sg.start;
    if (sg.K > 0) {
        // transpose-split: W[K,N] fp32 -> out[N,K] hi/lo
        const int n = local / sg.K;
        const int k = local - n * sg.K;
        bf16 h, l;
        split2(sg.src[(size_t)k * sg.N + n], h, l);
        sg.hi[local] = h; sg.lo[local] = l;
    } else {
        // elementwise split, float4 granularity
        float4 v = ((const float4*)sg.src)[local];
        bf16 h0,l0,h1,l1,h2,l2,h3,l3;
        split2(v.x, h0, l0); split2(v.y, h1, l1); split2(v.z, h2, l2); split2(v.w, h3, l3);
        bf162* ph = (bf162*)(sg.hi + (size_t)local * 4);
        bf162* pl = (bf162*)(sg.lo + (size_t)local * 4);
        ph[0] = bf162(h0, h1); ph[1] = bf162(h2, h3);
        pl[0] = bf162(l0, l1); pl[1] = bf162(l2, l3);
    }
}

__global__ void permutePtT_kernel(const float* __restrict__ Pq, const float* __restrict__ Pk,
                                  const float* __restrict__ Pv,
                                  bf16* __restrict__ hiT, bf16* __restrict__ loT) {
    int idx = blockIdx.x * 256 + threadIdx.x;
    if (idx >= NCAT * DM) return;
    int n = idx / DM;
    int d = idx - n * DM;
    int which = n / (HH*RR);
    int hn = n - which * (HH*RR);
    int h = hn >> 5;
    int r = hn & 31;
    const float* P = (which == 0) ? Pq : (which == 1) ? Pk : Pv;
    bf16 hh, ll;
    split2(P[((size_t)h * DM + d) * RR + r], hh, ll);
    hiT[idx] = hh; loT[idx] = ll;
}

// ---------------- split-K combine: sum fp32 partials, bias/gelu, split ----------------
__global__ void combine_kernel(const float* __restrict__ part, const float* __restrict__ bias,
                               float* __restrict__ Cf, bf16* __restrict__ Chi, bf16* __restrict__ Clo,
                               int Nd, int total, int nSlices, int doGelu) {
    int i = blockIdx.x * 256 + threadIdx.x;
    if (i >= total) return;
    float v = part[i];
    if (nSlices > 1) v += part[(size_t)total + i];
    if (nSlices > 2) v += part[2 * (size_t)total + i];
    if (bias) v += bias[i % Nd];
    if (doGelu) v = gelu_exact(v);
    if (Cf) Cf[i] = v;
    bf16 h, l;
    split2(v, h, l);
    Chi[i] = h; Clo[i] = l;
}

// ---------------- cp.async 3-stage split-bf16 GEMM (+ split-K) ----------------
#define KC 32
#define TILE_B (128 * KC * 2)          // 8192 bytes per tile
#define STAGE_B (4 * TILE_B)           // 32768 bytes per stage
#define SMEM_GEMM (3 * STAGE_B)        // 98304 bytes

__device__ __forceinline__ uint32_t sw32(int row, int seg) {
    return (uint32_t)(row * 64 + ((seg ^ ((row >> 1) & 3)) << 4));
}

__global__ __launch_bounds__(256)
void mma_gemm_kernel(const bf16* __restrict__ Ahi, const bf16* __restrict__ Alo,
                     const bf16* __restrict__ Bhi, const bf16* __restrict__ Blo,
                     const float* __restrict__ bias,
                     float* __restrict__ Cf, bf16* __restrict__ Chi, bf16* __restrict__ Clo,
                     float* __restrict__ Cpart,
                     int Md, int Nd, int Kd, int doGelu, int nSlices) {
    extern __shared__ char smraw[];
    const uint32_t smem_base = smem_u32(smraw);

    const int tid  = threadIdx.x;
    const int wid  = tid >> 5;
    const int lane = tid & 31;
    const int warpM = wid & 3;
    const int warpN = wid >> 2;
    const int rowBase = blockIdx.y * 128;
    const int colBase = blockIdx.x * 128;
    const int slice = blockIdx.z;
    const int chunksPer = (Kd / KC) / nSlices;
    const int kBase = slice * chunksPer * KC;

    const int lrow  = tid >> 1;
    const int lseg0 = (tid & 1) * 2;
    const bf16* gA  = Ahi + (size_t)(rowBase + lrow) * Kd + kBase;
    const bf16* gAl = Alo + (size_t)(rowBase + lrow) * Kd + kBase;
    const bf16* gB  = Bhi + (size_t)(colBase + lrow) * Kd + kBase;
    const bf16* gBl = Blo + (size_t)(colBase + lrow) * Kd + kBase;

    float acc[2][8][4];
    #pragma unroll
    for (int i = 0; i < 2; i++)
        #pragma unroll
        for (int j = 0; j < 8; j++)
            #pragma unroll
            for (int e = 0; e < 4; e++) acc[i][j][e] = 0.0f;

    const int arow0 = warpM * 32 + (lane & 15);
    const int alsel = lane >> 4;
    const int brow0 = warpN * 64 + (lane & 7) + ((lane >> 4) << 3);
    const int bcsel = (lane >> 3) & 1;

    // ---- prologue: prefetch chunks 0 and 1 ----
    #pragma unroll
    for (int p = 0; p < 2; p++) {
        const uint32_t sb = smem_base + p * STAGE_B;
        const int k0 = p * KC;
        #pragma unroll
        for (int si = 0; si < 2; si++) {
            const int seg = lseg0 + si;
            const uint32_t off = sw32(lrow, seg);
            cp16(sb + off,              gA  + k0 + seg * 8);
            cp16(sb + TILE_B + off,     gAl + k0 + seg * 8);
            cp16(sb + 2*TILE_B + off,   gB  + k0 + seg * 8);
            cp16(sb + 3*TILE_B + off,   gBl + k0 + seg * 8);
        }
        cp_commit();
    }
    cp_wait<1>();
    __syncthreads();

    int stage = 0;
    for (int c = 0; c < chunksPer; c++) {
        if (c + 2 < chunksPer) {
            const int ps = (stage + 2) % 3;
            const uint32_t sb = smem_base + ps * STAGE_B;
            const int k0 = (c + 2) * KC;
            #pragma unroll
            for (int si = 0; si < 2; si++) {
                const int seg = lseg0 + si;
                const uint32_t off = sw32(lrow, seg);
                cp16(sb + off,              gA  + k0 + seg * 8);
                cp16(sb + TILE_B + off,     gAl + k0 + seg * 8);
                cp16(sb + 2*TILE_B + off,   gB  + k0 + seg * 8);
                cp16(sb + 3*TILE_B + off,   gBl + k0 + seg * 8);
            }
            cp_commit();
        }

        const uint32_t sb = smem_base + stage * STAGE_B;
        #pragma unroll
        for (int kk = 0; kk < 2; kk++) {
            uint32_t ah[2][4], al[2][4], bh[16], bl[16];
            #pragma unroll
            for (int i = 0; i < 2; i++) {
                const int ar = arow0 + i * 16;
                const uint32_t off = sw32(ar, kk * 2 + alsel);
                ldsm4(ah[i], sb + off);
                ldsm4(al[i], sb + TILE_B + off);
            }
            #pragma unroll
            for (int g = 0; g < 4; g++) {
                const int br = brow0 + g * 16;
                const uint32_t off = sw32(br, kk * 2 + bcsel);
                ldsm4(&bh[g * 4], sb + 2*TILE_B + off);
                ldsm4(&bl[g * 4], sb + 3*TILE_B + off);
            }
            #pragma unroll
            for (int i = 0; i < 2; i++)
                #pragma unroll
                for (int j = 0; j < 8; j++) {
                    mma16816(acc[i][j], ah[i], &bh[j * 2]);
                    mma16816(acc[i][j], ah[i], &bl[j * 2]);
                    mma16816(acc[i][j], al[i], &bh[j * 2]);
                }
        }
        if (c + 2 < chunksPer) cp_wait<1>(); else cp_wait<0>();
        __syncthreads();
        stage = (stage + 1) % 3;
    }

    const int mrowW = rowBase + warpM * 32;
    const int ncolW = colBase + warpN * 64;
    if (nSlices > 1) {
        float* Cp = Cpart + (size_t)slice * Md * Nd;
        #pragma unroll
        for (int i = 0; i < 2; i++) {
            const int r0 = mrowW + i * 16 + (lane >> 2);
            const int r1 = r0 + 8;
            #pragma unroll
            for (int j = 0; j < 8; j++) {
                const int col = ncolW + j * 8 + (lane & 3) * 2;
                *(float2*)(Cp + (size_t)r0 * Nd + col) = make_float2(acc[i][j][0], acc[i][j][1]);
                *(float2*)(Cp + (size_t)r1 * Nd + col) = make_float2(acc[i][j][2], acc[i][j][3]);
            }
        }
        return;
    }
    #pragma unroll
    for (int i = 0; i < 2; i++) {
        const int r0 = mrowW + i * 16 + (lane >> 2);
        const int r1 = r0 + 8;
        #pragma unroll
        for (int j = 0; j < 8; j++) {
            const int col = ncolW + j * 8 + (lane & 3) * 2;
            float v0 = acc[i][j][0], v1 = acc[i][j][1];
            float v2 = acc[i][j][2], v3 = acc[i][j][3];
            if (bias) {
                const float b0 = bias[col], b1 = bias[col + 1];
                v0 += b0; v1 += b1; v2 += b0; v3 += b1;
            }
            if (doGelu) {
                v0 = gelu_exact(v0); v1 = gelu_exact(v1);
                v2 = gelu_exact(v2); v3 = gelu_exact(v3);
            }
            if (Cf) {
                *(float2*)(Cf + (size_t)r0 * Nd + col) = make_float2(v0, v1);
                *(float2*)(Cf + (size_t)r1 * Nd + col) = make_float2(v2, v3);
            }
            if (Chi) {
                uint32_t hh, ll;
                split_pack(v0, v1, hh, ll);
                *(uint32_t*)(Chi + (size_t)r0 * Nd + col) = hh;
                *(uint32_t*)(Clo + (size_t)r0 * Nd + col) = ll;
                split_pack(v2, v3, hh, ll);
                *(uint32_t*)(Chi + (size_t)r1 * Nd + col) = hh;
                *(uint32_t*)(Clo + (size_t)r1 * Nd + col) = ll;
            }
        }
    }
}

// ---------------- QKV stage 2: emits split bf16 Q(scaled)/K/V ----------------
__global__ __launch_bounds__(256)
void qkv2_kernel(const float* __restrict__ T,
                 const float* __restrict__ Vq, const float* __restrict__ Vk, const float* __restrict__ Vv,
                 const float* __restrict__ bq, const float* __restrict__ bk, const float* __restrict__ bv,
                 bf16* __restrict__ Qh, bf16* __restrict__ Ql,
                 bf16* __restrict__ Kh, bf16* __restrict__ Kl,
                 bf16* __restrict__ Vvh, bf16* __restrict__ Vvl) {
    __shared__ float Ts[HH*RR];
    const int bm = blockIdx.x;
    const int which = blockIdx.y;
    const float* Vw = (which == 0) ? Vq : (which == 1) ? Vk : Vv;
    const float* bw = (which == 0) ? bq : (which == 1) ? bk : bv;
    bf16* Oh = (which == 0) ? Qh : (which == 1) ? Kh : Vvh;
    bf16* Ol = (which == 0) ? Ql : (which == 1) ? Kl : Vvl;

    for (int i = threadIdx.x; i < HH*RR; i += 256)
        Ts[i] = T[(size_t)bm * NCAT + which * (HH*RR) + i];
    __syncthreads();

    const int b = bm / MM;
    const int m = bm - b * MM;
    const float sc = (which == 0) ? 0.125f : 1.0f;
    for (int o = threadIdx.x; o < HH * DHD; o += 256) {
        int h = o >> 6;
        int d = o & 63;
        float acc = bw[h * DHD + d];
        const float* w = Vw + (size_t)h * (RR * DHD) + d;
        const float* ts = Ts + h * RR;
        #pragma unroll
        for (int r = 0; r < RR; r++)
            acc += ts[r] * w[r * DHD];
        acc *= sc;
        bf16 hh, ll;
        split2(acc, hh, ll);
        const size_t idx = (((size_t)b * HH + h) * MM + m) * DHD + d;
        Oh[idx] = hh; Ol[idx] = ll;
    }
}

// ---------------- tensor-core flash attention, 3-stage cp.async KV pipeline ----------------
#define FT_B (64 * 64 * 2)          // 8192 bytes per KV tile
#define FSTAGE_B (4 * FT_B)         // 32768 per stage
#define SMEM_FLASH (3 * FSTAGE_B)   // 98304

__global__ __launch_bounds__(256)
void flash_mma_kernel(const bf16* __restrict__ Qh, const bf16* __restrict__ Ql,
                      const bf16* __restrict__ Kh, const bf16* __restrict__ Kl,
                      const bf16* __restrict__ Vh, const bf16* __restrict__ Vl,
                      const float* __restrict__ mask,
                      bf16* __restrict__ out_hi, bf16* __restrict__ out_lo) {
    extern __shared__ char smraw[];
    const uint32_t smem_base = smem_u32(smraw);
    __shared__ float sMk[3][64];

    const int t    = threadIdx.x;
    const int wid  = t >> 5;
    const int lane = t & 31;
    const int bh   = blockIdx.y;
    const int b    = bh / HH;
    const int h    = bh - b * HH;
    const int qBase = blockIdx.x * 128;

    // ---- stage Q (128x64 hi/lo) into stage-0 smem, load frags ----
    {
        bf16* smQh = (bf16*)smraw;
        bf16* smQl = (bf16*)(smraw + 2 * FT_B);
        const bf16* gQh = Qh + ((size_t)bh * MM + qBase) * DHD;
        const bf16* gQl = Ql + ((size_t)bh * MM + qBase) * DHD;
        #pragma unroll
        for (int i = 0; i < 4; i++) {
            const int idx = t + i * 256;
            const int row = idx >> 3;
            const int seg = idx & 7;
            const uint32_t off = (uint32_t)(row * 64 + ((seg ^ (row & 7)) << 3));
            *(uint4*)(smQh + off) = *(const uint4*)(gQh + row * 64 + seg * 8);
            *(uint4*)(smQl + off) = *(const uint4*)(gQl + row * 64 + seg * 8);
        }
    }
    __syncthreads();

    uint32_t qfh[4][4], qfl[4][4];
    {
        const int ar = wid * 16 + (lane & 15);
        const int alsel = lane >> 4;
        #pragma unroll
        for (int kk = 0; kk < 4; kk++) {
            const int cc = kk * 2 + alsel;
            const uint32_t off = (uint32_t)(ar * 128 + ((cc ^ (ar & 7)) << 4));
            ldsm4(qfh[kk], smem_base + off);
            ldsm4(qfl[kk], smem_base + 2 * FT_B + off);
        }
    }
    __syncthreads();

    float O[8][4];
    #pragma unroll
    for (int j = 0; j < 8; j++)
        #pragma unroll
        for (int e = 0; e < 4; e++) O[j][e] = 0.0f;
    float m0 = -1e30f, m1 = -1e30f, l0 = 0.0f, l1 = 0.0f;

    const int brow0 = (lane & 7) + ((lane >> 4) << 3);
    const int bcsel = (lane >> 3) & 1;
    const int kvrow = t >> 2;
    const int kvs0  = (t & 3) * 2;

    const bf16* gKh = Kh + ((size_t)bh * MM + kvrow) * DHD;
    const bf16* gKl = Kl + ((size_t)bh * MM + kvrow) * DHD;
    const bf16* gVh = Vh + ((size_t)bh * MM + kvrow) * DHD;
    const bf16* gVl = Vl + ((size_t)bh * MM + kvrow) * DHD;

    // prologue: prefetch KV chunks 0,1
    #pragma unroll
    for (int p = 0; p < 2; p++) {
        const uint32_t sb = smem_base + p * FSTAGE_B;
        const size_t koff = (size_t)p * 64 * DHD;
        #pragma unroll
        for (int si = 0; si < 2; si++) {
            const int seg = kvs0 + si;
            const uint32_t off = (uint32_t)(kvrow * 128 + ((seg ^ (kvrow & 7)) << 4));
            cp16(sb + off,            gKh + koff + seg * 8);
            cp16(sb + FT_B + off,     gKl + koff + seg * 8);
            cp16(sb + 2*FT_B + off,   gVh + koff + seg * 8);
            cp16(sb + 3*FT_B + off,   gVl + koff + seg * 8);
        }
        cp_commit();
        if (t < 64) sMk[p][t] = mask[(size_t)b * MM + p * 64 + t];
    }
    cp_wait<1>();
    __syncthreads();

    const int nIter = MM / 64;
    int stage = 0;
    for (int nb = 0; nb < nIter; nb++) {
        if (nb + 2 < nIter) {
            const int ps = (stage + 2) % 3;
            const uint32_t sb = smem_base + ps * FSTAGE_B;
            const size_t koff = (size_t)(nb + 2) * 64 * DHD;
            #pragma unroll
            for (int si = 0; si < 2; si++) {
                const int seg = kvs0 + si;
                const uint32_t off = (uint32_t)(kvrow * 128 + ((seg ^ (kvrow & 7)) << 4));
                cp16(sb + off,            gKh + koff + seg * 8);
                cp16(sb + FT_B + off,     gKl + koff + seg * 8);
                cp16(sb + 2*FT_B + off,   gVh + koff + seg * 8);
                cp16(sb + 3*FT_B + off,   gVl + koff + seg * 8);
            }
            cp_commit();
            if (t < 64) sMk[ps][t] = mask[(size_t)b * MM + (nb + 2) * 64 + t];
        }

        const uint32_t uK  = smem_base + stage * FSTAGE_B;
        const uint32_t uKl = uK + FT_B;
        const uint32_t uV  = uK + 2 * FT_B;
        const uint32_t uVl = uK + 3 * FT_B;

        // ---- S = Q @ K^T (3-pass split) ----
        float s[8][4];
        #pragma unroll
        for (int j = 0; j < 8; j++)
            #pragma unroll
            for (int e = 0; e < 4; e++) s[j][e] = 0.0f;

        #pragma unroll
        for (int kk = 0; kk < 4; kk++) {
            uint32_t kb[16], kbl[16];
            #pragma unroll
            for (int g = 0; g < 4; g++) {
                const int br = brow0 + g * 16;
                const int cc = kk * 2 + bcsel;
                const uint32_t off = (uint32_t)(br * 128 + ((cc ^ (br & 7)) << 4));
                ldsm4(&kb[g * 4],  uK + off);
                ldsm4(&kbl[g * 4], uKl + off);
            }
            #pragma unroll
            for (int j = 0; j < 8; j++) {
                mma16816(s[j], qfh[kk], &kb[j * 2]);
                mma16816(s[j], qfh[kk], &kbl[j * 2]);
                mma16816(s[j], qfl[kk], &kb[j * 2]);
            }
        }

        // ---- mask + online softmax ----
        const int c2 = (lane & 3) * 2;
        #pragma unroll
        for (int j = 0; j < 8; j++) {
            const float mka = sMk[stage][j * 8 + c2];
            const float mkb = sMk[stage][j * 8 + c2 + 1];
            s[j][0] += mka; s[j][1] += mkb; s[j][2] += mka; s[j][3] += mkb;
        }
        float mx0 = -1e30f, mx1 = -1e30f;
        #pragma unroll
        for (int j = 0; j < 8; j++) {
            mx0 = fmaxf(mx0, fmaxf(s[j][0], s[j][1]));
            mx1 = fmaxf(mx1, fmaxf(s[j][2], s[j][3]));
        }
        mx0 = fmaxf(mx0, __shfl_xor_sync(0xffffffffu, mx0, 1));
        mx0 = fmaxf(mx0, __shfl_xor_sync(0xffffffffu, mx0, 2));
        mx1 = fmaxf(mx1, __shfl_xor_sync(0xffffffffu, mx1, 1));
        mx1 = fmaxf(mx1, __shfl_xor_sync(0xffffffffu, mx1, 2));
        const float mn0 = fmaxf(m0, mx0);
        const float mn1 = fmaxf(m1, mx1);
        const float cr0 = __expf(m0 - mn0);
        const float cr1 = __expf(m1 - mn1);
        m0 = mn0; m1 = mn1;
        l0 *= cr0; l1 *= cr1;
        #pragma unroll
        for (int j = 0; j < 8; j++) {
            O[j][0] *= cr0; O[j][1] *= cr0;
            O[j][2] *= cr1; O[j][3] *= cr1;
        }

        // ---- P = exp(S - m), split+pack into A fragments ----
        uint32_t pahi[4][4], palo[4][4];
        #pragma unroll
        for (int j = 0; j < 8; j++) {
            const float p0 = __expf(s[j][0] - m0);
            const float p1 = __expf(s[j][1] - m0);
            const float p2 = __expf(s[j][2] - m1);
            const float p3 = __expf(s[j][3] - m1);
            l0 += p0 + p1;
            l1 += p2 + p3;
            const int kk = j >> 1, hf = (j & 1) * 2;
            split_pack(p0, p1, pahi[kk][hf],     palo[kk][hf]);
            split_pack(p2, p3, pahi[kk][hf + 1], palo[kk][hf + 1]);
        }

        // ---- O += P @ V (3-pass split) ----
        #pragma unroll
        for (int kk = 0; kk < 4; kk++) {
            uint32_t vh4[4][4], vl4[4][4];
            const int krow = kk * 16 + ((lane >> 3) & 1) * 8 + (lane & 7);
            #pragma unroll
            for (int g = 0; g < 4; g++) {
                const int cc = g * 2 + (lane >> 4);
                const uint32_t off = (uint32_t)(krow * 128 + ((cc ^ (krow & 7)) << 4));
                ldsm4t(vh4[g], uV + off);
                ldsm4t(vl4[g], uVl + off);
            }
            #pragma unroll
            for (int jn = 0; jn < 8; jn++) {
                const int g = jn >> 1, sub = (jn & 1) * 2;
                mma16816(O[jn], pahi[kk], &vh4[g][sub]);
                mma16816(O[jn], palo[kk], &vh4[g][sub]);
                mma16816(O[jn], pahi[kk], &vl4[g][sub]);
            }
        }
        if (nb + 2 < nIter) cp_wait<1>(); else cp_wait<0>();
        __syncthreads();
        stage = (stage + 1) % 3;
    }

    // ---- epilogue ----
    l0 += __shfl_xor_sync(0xffffffffu, l0, 1);
    l0 += __shfl_xor_sync(0xffffffffu, l0, 2);
    l1 += __shfl_xor_sync(0xffffffffu, l1, 1);
    l1 += __shfl_xor_sync(0xffffffffu, l1, 2);
    const float inv0 = 1.0f / l0;
    const float inv1 = 1.0f / l1;

    const int mrow0 = qBase + wid * 16 + (lane >> 2);
    const int mrow1 = mrow0 + 8;
    #pragma unroll
    for (int jn = 0; jn < 8; jn++) {
        const int col = h * DHD + jn * 8 + (lane & 3) * 2;
        uint32_t h01, l01, h23, l23;
        split_pack(O[jn][0] * inv0, O[jn][1] * inv0, h01, l01);
        split_pack(O[jn][2] * inv1, O[jn][3] * inv1, h23, l23);
        const size_t i0 = ((size_t)b * MM + mrow0) * DM + col;
        const size_t i1 = ((size_t)b * MM + mrow1) * DM + col;
        *(uint32_t*)(out_hi + i0) = h01;
        *(uint32_t*)(out_lo + i0) = l01;
        *(uint32_t*)(out_hi + i1) = h23;
        *(uint32_t*)(out_lo + i1) = l23;
    }
}

// ---------------- LayerNorm(xa + xb) * g + b; optional split output ----------------
__global__ __launch_bounds__(256)
void ln_kernel(const float* __restrict__ xa, const float* __restrict__ xb,
               const float* __restrict__ gw, const float* __restrict__ bw,
               float* __restrict__ out, bf16* __restrict__ ohi, bf16* __restrict__ olo) {
    const int row = blockIdx.x;
    const int t = threadIdx.x;
    const float* pa = xa + (size_t)row * DM;
    const float* pb = xb + (size_t)row * DM;

    float v0 = pa[t]       + pb[t];
    float v1 = pa[t + 256] + pb[t + 256];
    float v2 = pa[t + 512] + pb[t + 512];

    float s  = v0 + v1 + v2;
    float ss = v0 * v0 + v1 * v1 + v2 * v2;
    #pragma unroll
    for (int off = 16; off > 0; off >>= 1) {
        s  += __shfl_xor_sync(0xffffffffu, s,  off);
        ss += __shfl_xor_sync(0xffffffffu, ss, off);
    }
    __shared__ float wsum[8], wsq[8], stats[2];
    int warp = t >> 5;
    if ((t & 31) == 0) { wsum[warp] = s; wsq[warp] = ss; }
    __syncthreads();
    if (t == 0) {
        float S = 0.f, SS = 0.f;
        #pragma unroll
        for (int w = 0; w < 8; w++) { S += wsum[w]; SS += wsq[w]; }
        float mu = S * (1.0f / DM);
        float var = SS * (1.0f / DM) - mu * mu;
        stats[0] = mu;
        stats[1] = rsqrtf(var + 1e-12f);
    }
    __syncthreads();
    float mu = stats[0], rstd = stats[1];
    float* po = out + (size_t)row * DM;
    float r0 = (v0 - mu) * rstd * gw[t]       + bw[t];
    float r1 = (v1 - mu) * rstd * gw[t + 256] + bw[t + 256];
    float r2 = (v2 - mu) * rstd * gw[t + 512] + bw[t + 512];
    po[t] = r0; po[t + 256] = r1; po[t + 512] = r2;
    if (ohi) {
        bf16 hh, ll;
        split2(r0, hh, ll); ohi[(size_t)row*DM + t]       = hh; olo[(size_t)row*DM + t]       = ll;
        split2(r1, hh, ll); ohi[(size_t)row*DM + t + 256] = hh; olo[(size_t)row*DM + t + 256] = ll;
        split2(r2, hh, ll); ohi[(size_t)row*DM + t + 512] = hh; olo[(size_t)row*DM + t + 512] = ll;
    }
}

// ---------------- launch ----------------
static inline void launch_mma(const bf16* Ahi, const bf16* Alo, const bf16* Bhi, const bf16* Blo,
                              const float* bias, float* Cf, bf16* Chi, bf16* Clo,
                              int Md, int Nd, int Kd, int doGelu,
                              float* Cpart = nullptr, int nSlices = 1) {
    dim3 grid(Nd / 128, Md / 128, nSlices);
    mma_gemm_kernel<<<grid, 256, SMEM_GEMM>>>(Ahi, Alo, Bhi, Blo, bias, Cf, Chi, Clo, Cpart,
                                              Md, Nd, Kd, doGelu, nSlices);
}

extern "C" void kernel_launch(void* const* d_in, const int* in_sizes, int n_in,
                              void* d_out, int out_size) {
    const float* x    = (const float*)d_in[0];
    const float* mask = (const float*)d_in[1];
    const float* Pq   = (const float*)d_in[2];
    const float* Vq   = (const float*)d_in[3];
    const float* bq   = (const float*)d_in[4];
    const float* Pk   = (const float*)d_in[5];
    const float* Vk   = (const float*)d_in[6];
    const float* bk   = (const float*)d_in[7];
    const float* Pv   = (const float*)d_in[8];
    const float* Vv   = (const float*)d_in[9];
    const float* bv   = (const float*)d_in[10];
    const float* Uo   = (const float*)d_in[11];
    const float* Vo   = (const float*)d_in[12];
    const float* bo   = (const float*)d_in[13];
    const float* U1   = (const float*)d_in[14];
    const float* V1   = (const float*)d_in[15];
    const float* b1   = (const float*)d_in[16];
    const float* U2   = (const float*)d_in[17];
    const float* V2   = (const float*)d_in[18];
    const float* b2   = (const float*)d_in[19];
    const float* ln1g = (const float*)d_in[20];
    const float* ln1b = (const float*)d_in[21];
    const float* ln2g = (const float*)d_in[22];
    const float* ln2b = (const float*)d_in[23];

    static bool attrSet = false;
    if (!attrSet) {
        cudaFuncSetAttribute(mma_gemm_kernel, cudaFuncAttributeMaxDynamicSharedMemorySize, SMEM_GEMM);
        cudaFuncSetAttribute(flash_mma_kernel, cudaFuncAttributeMaxDynamicSharedMemorySize, SMEM_FLASH);
        attrSet = true;
    }

    float *pT, *pQ, *pK, *pV, *pTmp, *pX1;
    cudaGetSymbolAddress((void**)&pT,   g_T);
    cudaGetSymbolAddress((void**)&pQ,   g_Q);
    cudaGetSymbolAddress((void**)&pK,   g_K);
    cudaGetSymbolAddress((void**)&pV,   g_V);
    cudaGetSymbolAddress((void**)&pTmp, g_tmp);
    cudaGetSymbolAddress((void**)&pX1,  g_x1);

    bf16* qh = (bf16*)pQ;  bf16* ql = qh + (size_t)BMTOT * DM;
    bf16* kh = (bf16*)pK;  bf16* kl = kh + (size_t)BMTOT * DM;
    bf16* vh = (bf16*)pV;  bf16* vl = vh + (size_t)BMTOT * DM;

    bf16 *xsH,*xsL,*asH,*asL,*msH,*msL,*x1H,*x1L,*hsH,*hsL;
    bf16 *ptH,*ptL,*uoH,*uoL,*voH,*voL,*u1H,*u1L,*v1H,*v1L,*u2H,*u2L,*v2H,*v2L;
    cudaGetSymbolAddress((void**)&xsH, g_xs_hi);  cudaGetSymbolAddress((void**)&xsL, g_xs_lo);
    cudaGetSymbolAddress((void**)&asH, g_as_hi);  cudaGetSymbolAddress((void**)&asL, g_as_lo);
    cudaGetSymbolAddress((void**)&msH, g_ms_hi);  cudaGetSymbolAddress((void**)&msL, g_ms_lo);
    cudaGetSymbolAddress((void**)&x1H, g_x1s_hi); cudaGetSymbolAddress((void**)&x1L, g_x1s_lo);
    cudaGetSymbolAddress((void**)&hsH, g_hs_hi);  cudaGetSymbolAddress((void**)&hsL, g_hs_lo);
    cudaGetSymbolAddress((void**)&ptH, g_ptT_hi); cudaGetSymbolAddress((void**)&ptL, g_ptT_lo);
    cudaGetSymbolAddress((void**)&uoH, g_uoT_hi); cudaGetSymbolAddress((void**)&uoL, g_uoT_lo);
    cudaGetSymbolAddress((void**)&voH, g_voT_hi); cudaGetSymbolAddress((void**)&voL, g_voT_lo);
    cudaGetSymbolAddress((void**)&u1H, g_u1T_hi); cudaGetSymbolAddress((void**)&u1L, g_u1T_lo);
    cudaGetSymbolAddress((void**)&v1H, g_v1T_hi); cudaGetSymbolAddress((void**)&v1L, g_v1T_lo);
    cudaGetSymbolAddress((void**)&u2H, g_u2T_hi); cudaGetSymbolAddress((void**)&u2L, g_u2T_lo);
    cudaGetSymbolAddress((void**)&v2H, g_v2T_hi); cudaGetSymbolAddress((void**)&v2L, g_v2T_lo);

    // ---- conversions: P permute + fused transposes + x split (2 launches) ----
    permutePtT_kernel<<<(NCAT * DM + 255) / 256, 256>>>(Pq, Pk, Pv, ptH, ptL);
    {
        ConvArgs ca;
        int off = 0;
        auto add = [&](int i, const float* src, bf16* hi, bf16* lo, int K, int N, int len) {
            ca.seg[i].src = src; ca.seg[i].hi = hi; ca.seg[i].lo = lo;
            ca.seg[i].K = K; ca.seg[i].N = N; ca.seg[i].start = off;
            off += len;
        };
        add(0, Uo, uoH, uoL, DM,  RFF, DM*RFF);
        add(1, Vo, voH, voL, RFF, DM,  RFF*DM);
        add(2, U1, u1H, u1L, DM,  RFF, DM*RFF);
        add(3, V1, v1H, v1L, RFF, DFF, RFF*DFF);
        add(4, U2, u2H, u2L, DFF, RFF, DFF*RFF);
        add(5, V2, v2H, v2L, RFF, DM,  RFF*DM);
        add(6, x,  xsH, xsL, 0,   0,   BMTOT*DM/4);
        ca.total = off;
        fused_convert_kernel<<<(ca.total + 255) / 256, 256>>>(ca);
    }

    // ---- 1) T = x @ Pt ----
    launch_mma(xsH, xsL, ptH, ptL, nullptr, pT, nullptr, nullptr, BMTOT, NCAT, DM, 0);

    // ---- 2) QKV stage 2 ----
    qkv2_kernel<<<dim3(BMTOT, 3), 256>>>(pT, Vq, Vk, Vv, bq, bk, bv, qh, ql, kh, kl, vh, vl);

    // ---- 3) flash attention ----
    flash_mma_kernel<<<dim3(MM / 128, BB * HH), 256, SMEM_FLASH>>>(qh, ql, kh, kl, vh, vl, mask, asH, asL);

    // ---- 4) Wo low-rank + LN1 ----
    launch_mma(asH, asL, uoH, uoL, nullptr, nullptr, nullptr, nullptr, BMTOT, RFF, DM, 0, pT, 2);
    combine_kernel<<<(BMTOT*RFF + 255)/256, 256>>>(pT, nullptr, nullptr, msH, msL, RFF, BMTOT*RFF, 2, 0);
    launch_mma(msH, msL, voH, voL, bo, pTmp, nullptr, nullptr, BMTOT, DM, RFF, 0);
    ln_kernel<<<BMTOT, 256>>>(x, pTmp, ln1g, ln1b, pX1, x1H, x1L);

    // ---- 5) FFN ----
    launch_mma(x1H, x1L, u1H, u1L, nullptr, nullptr, nullptr, nullptr, BMTOT, RFF, DM, 0, pT, 2);
    combine_kernel<<<(BMTOT*RFF + 255)/256, 256>>>(pT, nullptr, nullptr, msH, msL, RFF, BMTOT*RFF, 2, 0);
    launch_mma(msH, msL, v1H, v1L, b1, nullptr, hsH, hsL, BMTOT, DFF, RFF, 1);
    launch_mma(hsH, hsL, u2H, u2L, nullptr, nullptr, nullptr, nullptr, BMTOT, RFF, DFF, 0, pT, 3);
    combine_kernel<<<(BMTOT*RFF + 255)/256, 256>>>(pT, nullptr, nullptr, msH, msL, RFF, BMTOT*RFF, 3, 0);
    launch_mma(msH, msL, v2H, v2L, b2, pTmp, nullptr, nullptr, BMTOT, DM, RFF, 0);
    ln_kernel<<<BMTOT, 256>>>(pX1, pTmp, ln2g, ln2b, (float*)d_out, nullptr, nullptr);
}